// round 2
// baseline (speedup 1.0000x reference)
#include <cuda_runtime.h>
#include <cstdint>
#include <cstddef>

#define NSITES 131072
#define HID    512
#define KTAPS  9
#define GROUPS 32
#define EPS    1e-5f

// Ping-pong activation scratch (device globals: allocation-free rule).
__device__ float g_bufA[(size_t)NSITES * HID];
__device__ float g_bufB[(size_t)NSITES * HID];

// ---- packed fp32x2 helpers (sm_100+: doubles fp32 FMA throughput vs 3-reg FFMA) ----
__device__ __forceinline__ unsigned long long pack_dup(float a) {
    unsigned long long r;
    asm("mov.b64 %0, {%1, %1};" : "=l"(r) : "f"(a));
    return r;
}
__device__ __forceinline__ void fmax2(unsigned long long& d, unsigned long long a,
                                      unsigned long long b) {
    asm("fma.rn.f32x2 %0, %1, %2, %0;" : "+l"(d) : "l"(a), "l"(b));
}

// ============================================================================
// Gather-GEMM: Y[M=128 tile, N=128 tile] = sum_k A_gather[m,k] * W[k,n]
//   K = 9*CIN, A row for k = X[nbr[m][k/CIN]][k%CIN]  (zero row if idx < 0)
//   W is [K, 512] row-major (exactly the dataset layout).
// 256 threads, each computes an 8x8 microtile via fp32x2 packed FMA.
// ============================================================================
template<int CIN>
__global__ __launch_bounds__(256, 2)
void subm_gemm(const float* __restrict__ X, const int* __restrict__ nbr,
               const float* __restrict__ W, float* __restrict__ Y)
{
    constexpr int KTOT = KTAPS * CIN;
    constexpr int NCH  = KTOT / 16;     // 16 | CIN, chunks never cross a tap

    __shared__ float As[16][128];       // transposed: As[k][m]
    __shared__ float Bs[16][128];       // Bs[k][n]
    __shared__ int   idx_s[128 * KTAPS];

    const int tid = threadIdx.x;
    const int m0  = blockIdx.x * 128;
    const int n0  = blockIdx.y * 128;

    // rulebook rows for this M tile (coalesced: nbr is [N][9] row-major)
    for (int i = tid; i < 128 * KTAPS; i += 256)
        idx_s[i] = nbr[(size_t)m0 * KTAPS + i];
    __syncthreads();

    const int arow = tid & 127;         // A: one row, two float4 column slots
    const int ac4  = tid >> 7;          // 0 or 1
    const int bk   = tid >> 5;          // B: rows bk, bk+8
    const int bn4  = tid & 31;
    const int ty   = tid >> 4;          // microtile rows ty*8..+7
    const int tx   = tid & 15;          // microtile cols tx*8..+7

    unsigned long long acc[8][4];       // f32x2 accumulators: 8 rows x 4 col-pairs
    #pragma unroll
    for (int i = 0; i < 8; i++)
        #pragma unroll
        for (int j = 0; j < 4; j++) acc[i][j] = 0ull;

    float4 aR0, aR1, bR0, bR1;

    auto load_g = [&](int ch) {
        const int k0  = ch * 16;
        const int tap = k0 / CIN;
        const int c0  = k0 - tap * CIN;
        const int g   = idx_s[arow * KTAPS + tap];
        if (g >= 0) {
            const float4* pa = reinterpret_cast<const float4*>(X + (size_t)g * CIN + c0);
            aR0 = pa[ac4];
            aR1 = pa[ac4 + 2];
        } else {
            aR0 = make_float4(0.f, 0.f, 0.f, 0.f);
            aR1 = aR0;
        }
        const float* wb = W + (size_t)(k0 + bk) * HID + n0;
        bR0 = *reinterpret_cast<const float4*>(wb + bn4 * 4);
        bR1 = *reinterpret_cast<const float4*>(wb + (size_t)8 * HID + bn4 * 4);
    };

    auto store_s = [&]() {
        const int kb = ac4 * 4;
        As[kb + 0][arow] = aR0.x;  As[kb + 1][arow] = aR0.y;
        As[kb + 2][arow] = aR0.z;  As[kb + 3][arow] = aR0.w;
        As[kb + 8][arow] = aR1.x;  As[kb + 9][arow] = aR1.y;
        As[kb +10][arow] = aR1.z;  As[kb +11][arow] = aR1.w;
        *reinterpret_cast<float4*>(&Bs[bk    ][bn4 * 4]) = bR0;
        *reinterpret_cast<float4*>(&Bs[bk + 8][bn4 * 4]) = bR1;
    };

    auto compute = [&]() {
        #pragma unroll
        for (int kk = 0; kk < 16; kk++) {
            float4 b0 = *reinterpret_cast<const float4*>(&Bs[kk][tx * 8]);
            float4 b1 = *reinterpret_cast<const float4*>(&Bs[kk][tx * 8 + 4]);
            unsigned long long B2[4];
            B2[0] = *reinterpret_cast<unsigned long long*>(&b0.x);
            B2[1] = *reinterpret_cast<unsigned long long*>(&b0.z);
            B2[2] = *reinterpret_cast<unsigned long long*>(&b1.x);
            B2[3] = *reinterpret_cast<unsigned long long*>(&b1.z);
            float4 a0 = *reinterpret_cast<const float4*>(&As[kk][ty * 8]);
            float4 a1 = *reinterpret_cast<const float4*>(&As[kk][ty * 8 + 4]);
            float am[8] = {a0.x, a0.y, a0.z, a0.w, a1.x, a1.y, a1.z, a1.w};
            #pragma unroll
            for (int i = 0; i < 8; i++) {
                unsigned long long ad = pack_dup(am[i]);
                fmax2(acc[i][0], ad, B2[0]);
                fmax2(acc[i][1], ad, B2[1]);
                fmax2(acc[i][2], ad, B2[2]);
                fmax2(acc[i][3], ad, B2[3]);
            }
        }
    };

    // software-pipelined mainloop: LDG for chunk ch overlaps compute of ch-1
    load_g(0);
    store_s();
    __syncthreads();
    for (int ch = 1; ch < NCH; ch++) {
        load_g(ch);
        compute();
        __syncthreads();
        store_s();
        __syncthreads();
    }
    compute();

    // epilogue: raw GEMM result (GroupNorm handled by the fused per-site kernel)
    #pragma unroll
    for (int i = 0; i < 8; i++) {
        float2 c0 = *reinterpret_cast<float2*>(&acc[i][0]);
        float2 c1 = *reinterpret_cast<float2*>(&acc[i][1]);
        float2 c2 = *reinterpret_cast<float2*>(&acc[i][2]);
        float2 c3 = *reinterpret_cast<float2*>(&acc[i][3]);
        float* yp = Y + (size_t)(m0 + ty * 8 + i) * HID + n0 + tx * 8;
        *reinterpret_cast<float4*>(yp)     = make_float4(c0.x, c0.y, c1.x, c1.y);
        *reinterpret_cast<float4*>(yp + 4) = make_float4(c2.x, c2.y, c3.x, c3.y);
    }
}

// ============================================================================
// GroupNorm(32 groups x 16 ch, population variance) + ReLU.
// One thread per (site, group): 16 contiguous channels -> fully thread-local.
// t*16 == site*512 + group*16.
// ============================================================================
__global__ void gn_relu(const float* __restrict__ Yin, float* __restrict__ Yout,
                        const float* __restrict__ gamma, const float* __restrict__ beta)
{
    const int t = blockIdx.x * blockDim.x + threadIdx.x;   // exact grid, no guard
    const int g = t & (GROUPS - 1);
    const float4* p = reinterpret_cast<const float4*>(Yin + (size_t)t * 16);
    float v[16];
    *reinterpret_cast<float4*>(&v[0])  = p[0];
    *reinterpret_cast<float4*>(&v[4])  = p[1];
    *reinterpret_cast<float4*>(&v[8])  = p[2];
    *reinterpret_cast<float4*>(&v[12]) = p[3];

    float s = 0.f, ss = 0.f;
    #pragma unroll
    for (int j = 0; j < 16; j++) { s += v[j]; ss += v[j] * v[j]; }
    const float mu  = s * (1.f / 16.f);
    const float var = ss * (1.f / 16.f) - mu * mu;
    const float rs  = rsqrtf(var + EPS);

    const float* gm = gamma + g * 16;
    const float* bt = beta  + g * 16;
    #pragma unroll
    for (int j = 0; j < 16; j++)
        v[j] = fmaxf(fmaf((v[j] - mu) * rs, gm[j], bt[j]), 0.f);

    float4* q = reinterpret_cast<float4*>(Yout + (size_t)t * 16);
    q[0] = *reinterpret_cast<float4*>(&v[0]);
    q[1] = *reinterpret_cast<float4*>(&v[4]);
    q[2] = *reinterpret_cast<float4*>(&v[8]);
    q[3] = *reinterpret_cast<float4*>(&v[12]);
}

// ============================================================================
// kernel_launch: 8 x (gather-GEMM -> GN+ReLU), ping-pong scratch buffers.
// All launches on the default stream; graph-capturable, allocation-free.
// ============================================================================
extern "C" void kernel_launch(void* const* d_in, const int* in_sizes, int n_in,
                              void* d_out, int out_size)
{
    const float* feat  = (const float*)d_in[0];   // [131072, 256]
    const int*   nbr   = (const int*)  d_in[1];   // [131072, 9]
    const float* w0    = (const float*)d_in[2];   // [9, 256, 512] = [2304, 512]
    const float* wrest = (const float*)d_in[3];   // [7, 9, 512, 512]
    const float* gamma = (const float*)d_in[4];   // [8, 512]
    const float* beta  = (const float*)d_in[5];   // [8, 512]
    float* out = (float*)d_out;                   // [131072, 512] fp32

    float *bufA = nullptr, *bufB = nullptr;
    cudaGetSymbolAddress((void**)&bufA, g_bufA);
    cudaGetSymbolAddress((void**)&bufB, g_bufB);

    const dim3 ggrid(NSITES / 128, HID / 128);
    const int  gn_blocks = NSITES * GROUPS / 256;

    // layer 0: CIN=256
    subm_gemm<256><<<ggrid, 256>>>(feat, nbr, w0, bufA);
    gn_relu<<<gn_blocks, 256>>>(bufA, bufA, gamma, beta);

    const float* x = bufA;
    float*       y = bufB;
    for (int l = 1; l < 8; l++) {
        const float* wl = wrest + (size_t)(l - 1) * KTAPS * HID * HID;
        subm_gemm<512><<<ggrid, 256>>>(x, nbr, wl, y);
        float* gout = (l == 7) ? out : y;
        gn_relu<<<gn_blocks, 256>>>(y, gout, gamma + l * HID, beta + l * HID);
        x = y;
        y = (y == bufB) ? bufA : bufB;
    }
}

// round 4
// speedup vs baseline: 3.4422x; 3.4422x over previous
#include <cuda_runtime.h>
#include <cstdint>
#include <cstddef>

#define NSITES 131072
#define HID    512
#define KTAPS  9
#define EPS    1e-5f

// ---------------------------------------------------------------------------
// Device-global scratch (allocation-free rule)
// ---------------------------------------------------------------------------
__device__ __align__(16) float g_bufA[(size_t)NSITES * HID];
__device__ __align__(16) float g_bufB[(size_t)NSITES * HID];
__device__ __align__(16) float g_featr[(size_t)NSITES * 256];
#define W0_ELEMS ((size_t)2304 * 512)
#define WL_ELEMS ((size_t)4608 * 512)
__device__ __align__(16) float g_W[W0_ELEMS + 7 * WL_ELEMS];

// ---------------------------------------------------------------------------
// Helpers (all baseline PTX — valid on .target sm_103)
// ---------------------------------------------------------------------------
__device__ __forceinline__ uint32_t smem_u32(const void* p) {
    uint32_t a;
    asm("{ .reg .u64 t; cvta.to.shared.u64 t, %1; cvt.u32.u64 %0, t; }" : "=r"(a) : "l"(p));
    return a;
}
__device__ __forceinline__ float tf32_rn(float v) {
    uint32_t o;
    asm("cvt.rna.tf32.f32 %0, %1;" : "=r"(o) : "f"(v));
    return __uint_as_float(o);
}
__device__ __forceinline__ void cp16(uint32_t dst, const void* src, int nbytes) {
    asm volatile("cp.async.cg.shared.global [%0], [%1], 16, %2;"
                 :: "r"(dst), "l"(src), "r"(nbytes));
}
#define CP_COMMIT() asm volatile("cp.async.commit_group;" ::: "memory")
#define CP_WAIT(n)  asm volatile("cp.async.wait_group %0;" :: "n"(n) : "memory")

// m16n8k8 tf32 MMA, fp32 accumulate (sm_80+ baseline PTX).
__device__ __forceinline__ void mma8(float& d0, float& d1, float& d2, float& d3,
                                     float a0, float a1, float a2, float a3,
                                     float b0, float b1) {
    asm volatile(
        "mma.sync.aligned.m16n8k8.row.col.f32.tf32.tf32.f32 "
        "{%0,%1,%2,%3}, {%4,%5,%6,%7}, {%8,%9}, {%0,%1,%2,%3};"
        : "+f"(d0), "+f"(d1), "+f"(d2), "+f"(d3)
        : "r"(__float_as_uint(a0)), "r"(__float_as_uint(a1)),
          "r"(__float_as_uint(a2)), "r"(__float_as_uint(a3)),
          "r"(__float_as_uint(b0)), "r"(__float_as_uint(b1)));
}

// ---------------------------------------------------------------------------
// SMEM layout (floats). A rows padded to 20 (80B), B rows to 136 (544B):
// both verified conflict-free for the m16n8k8 fragment access pattern.
// ---------------------------------------------------------------------------
#define A_STRIDE 20
#define B_STRIDE 136
#define A_SZ (256 * A_STRIDE)          // 5120 floats / stage
#define B_SZ (16 * B_STRIDE)           // 2176 floats / stage
#define STAGES 3
#define SG_OFF (STAGES * (A_SZ + B_SZ))            // 21888
#define SB_OFF (SG_OFF + 128)                      // 22016
#define IX_OFF (SB_OFF + 128)                      // 22144
#define SMEM_FLOATS (IX_OFF + 256 * KTAPS)         // 24448
#define SMEM_BYTES  (SMEM_FLOATS * 4)              // 97792

// ===========================================================================
// Fused gather-GEMM (mma.sync tf32) + GroupNorm + ReLU.
// CTA: 256 sites x 128 out-channels, 8 warps (warp tile 64x64).
// ===========================================================================
template<int CIN, bool ROUND_OUT>
__global__ __launch_bounds__(256, 1)
void spconv_mma(const float* __restrict__ X, const int* __restrict__ nbr,
                const float* __restrict__ W,       // [KTAPS*CIN, 512] row-major, tf32-rounded
                const float* __restrict__ gamma, const float* __restrict__ beta,
                float* __restrict__ Y)
{
    constexpr int KTOT = KTAPS * CIN;
    constexpr int NCH  = KTOT / 16;     // k-chunks of 16
    constexpr int CPT  = CIN / 16;      // chunks per tap

    extern __shared__ float sm[];
    const uint32_t smbase = smem_u32(sm);
    int* sidx = (int*)(sm + IX_OFF);

    const int tid = threadIdx.x;
    const int m0  = blockIdx.x * 256;
    const int n0  = blockIdx.y * 128;

    for (int i = tid; i < 128; i += 256) {
        sm[SG_OFF + i] = gamma[n0 + i];
        sm[SB_OFF + i] = beta[n0 + i];
    }
    for (int i = tid; i < 256 * KTAPS; i += 256)
        sidx[i] = nbr[(size_t)m0 * KTAPS + i];
    __syncthreads();

    const int warp = tid >> 5, lane = tid & 31;
    const int wm  = (warp >> 1) * 64;   // warp M offset: 0,64,128,192
    const int wn  = (warp & 1) * 64;    // warp N offset: 0,64
    const int gid = lane >> 2;          // 0..7
    const int q   = lane & 3;           // 0..3

    float d[4][8][4];
    #pragma unroll
    for (int i = 0; i < 4; i++)
        #pragma unroll
        for (int j = 0; j < 8; j++)
            #pragma unroll
            for (int r = 0; r < 4; r++) d[i][j][r] = 0.f;

    // ---- async load of one k16 chunk into stage s ----
    auto load_chunk = [&](int ch, int s) {
        const int tap = ch / CPT;
        const int c0  = (ch - tap * CPT) * 16;
        const uint32_t abase = smbase + (uint32_t)s * (A_SZ * 4);
        #pragma unroll
        for (int t = 0; t < 4; t++) {               // 1024 A granules
            const int g = tid + (t << 8);
            const int row = g >> 2, kq = g & 3;
            const int nid = sidx[row * KTAPS + tap];
            const float* src = X + (size_t)(nid < 0 ? 0 : nid) * CIN + c0 + kq * 4;
            cp16(abase + (uint32_t)(row * 80 + kq * 16), src, nid < 0 ? 0 : 16);
        }
        const uint32_t bbase = smbase + (uint32_t)(STAGES * A_SZ * 4) + (uint32_t)s * (B_SZ * 4);
        const float* wb = W + (size_t)ch * 16 * HID + n0;
        #pragma unroll
        for (int t = 0; t < 2; t++) {               // 512 B granules
            const int g = tid + (t << 8);
            const int kr = g >> 5, ns = g & 31;
            cp16(bbase + (uint32_t)(kr * 544 + ns * 16), wb + (size_t)kr * HID + ns * 4, 16);
        }
    };

    // ---- compute one k16 chunk from stage s ----
    auto compute = [&](int s) {
        const float* Af = sm + s * A_SZ;
        const float* Bf = sm + STAGES * A_SZ + s * B_SZ;
        #pragma unroll
        for (int ks = 0; ks < 2; ks++) {
            float a[4][4];
            #pragma unroll
            for (int mt = 0; mt < 4; mt++) {
                const int r = wm + mt * 16 + gid;
                const int c = ks * 8 + q;
                a[mt][0] = Af[r * A_STRIDE + c];
                a[mt][1] = Af[(r + 8) * A_STRIDE + c];
                a[mt][2] = Af[r * A_STRIDE + c + 4];
                a[mt][3] = Af[(r + 8) * A_STRIDE + c + 4];
            }
            #pragma unroll
            for (int nt = 0; nt < 8; nt++) {
                const int n = wn + nt * 8 + gid;
                const int k = ks * 8 + q;
                const float b0 = Bf[k * B_STRIDE + n];
                const float b1 = Bf[(k + 4) * B_STRIDE + n];
                #pragma unroll
                for (int mt = 0; mt < 4; mt++)
                    mma8(d[mt][nt][0], d[mt][nt][1], d[mt][nt][2], d[mt][nt][3],
                         a[mt][0], a[mt][1], a[mt][2], a[mt][3], b0, b1);
            }
        }
    };

    // ---- 3-stage pipelined mainloop ----
    load_chunk(0, 0); CP_COMMIT();
    load_chunk(1, 1); CP_COMMIT();
    #pragma unroll 3
    for (int ch = 0; ch < NCH; ch++) {
        CP_WAIT(1);                     // stage ch resident
        __syncthreads();                // all warps done with stage (ch-1)%3 too
        if (ch + 2 < NCH) load_chunk(ch + 2, (ch + 2) % STAGES);
        CP_COMMIT();
        compute(ch % STAGES);
    }

    // ---- fused GroupNorm(16-ch groups) + ReLU epilogue ----
    // C frag: regs {0,1}=row gid cols 2q,2q+1; regs {2,3}=row gid+8.
    // One 16-ch group = two adjacent n8 tiles x 4 quad lanes.
    #pragma unroll
    for (int mt = 0; mt < 4; mt++) {
        #pragma unroll
        for (int h = 0; h < 2; h++) {
            const int row = m0 + wm + mt * 16 + gid + h * 8;
            float* yr = Y + (size_t)row * HID + n0 + wn;
            #pragma unroll
            for (int g = 0; g < 4; g++) {
                const float v0 = d[mt][2 * g    ][2 * h];
                const float v1 = d[mt][2 * g    ][2 * h + 1];
                const float v2 = d[mt][2 * g + 1][2 * h];
                const float v3 = d[mt][2 * g + 1][2 * h + 1];
                float s  = v0 + v1 + v2 + v3;
                float ss = v0 * v0 + v1 * v1 + v2 * v2 + v3 * v3;
                s  += __shfl_xor_sync(0xffffffffu, s, 1);
                ss += __shfl_xor_sync(0xffffffffu, ss, 1);
                s  += __shfl_xor_sync(0xffffffffu, s, 2);
                ss += __shfl_xor_sync(0xffffffffu, ss, 2);
                const float mu  = s * (1.f / 16.f);
                const float var = ss * (1.f / 16.f) - mu * mu;
                const float rs  = rsqrtf(var + EPS);
                const int cb = wn + 16 * g + 2 * q;       // local col in [0,128)
                float o0 = fmaxf(fmaf((v0 - mu) * rs, sm[SG_OFF + cb],     sm[SB_OFF + cb]),     0.f);
                float o1 = fmaxf(fmaf((v1 - mu) * rs, sm[SG_OFF + cb + 1], sm[SB_OFF + cb + 1]), 0.f);
                float o2 = fmaxf(fmaf((v2 - mu) * rs, sm[SG_OFF + cb + 8], sm[SB_OFF + cb + 8]), 0.f);
                float o3 = fmaxf(fmaf((v3 - mu) * rs, sm[SG_OFF + cb + 9], sm[SB_OFF + cb + 9]), 0.f);
                if (ROUND_OUT) {
                    o0 = tf32_rn(o0); o1 = tf32_rn(o1);
                    o2 = tf32_rn(o2); o3 = tf32_rn(o3);
                }
                *(float2*)(yr + 16 * g + 2 * q)     = make_float2(o0, o1);
                *(float2*)(yr + 16 * g + 8 + 2 * q) = make_float2(o2, o3);
            }
        }
    }
}

// ---------------------------------------------------------------------------
// tf32-RNA rounding copy (float4 per thread)
// ---------------------------------------------------------------------------
__global__ void round_copy(const float* __restrict__ src, float* __restrict__ dst, int n4)
{
    const int t = blockIdx.x * blockDim.x + threadIdx.x;
    if (t >= n4) return;
    float4 v = ((const float4*)src)[t];
    v.x = tf32_rn(v.x); v.y = tf32_rn(v.y);
    v.z = tf32_rn(v.z); v.w = tf32_rn(v.w);
    ((float4*)dst)[t] = v;
}

// ===========================================================================
// kernel_launch: prep (round) + 8 fused layers, ping-pong buffers.
// ===========================================================================
extern "C" void kernel_launch(void* const* d_in, const int* in_sizes, int n_in,
                              void* d_out, int out_size)
{
    const float* feat  = (const float*)d_in[0];   // [131072, 256]
    const int*   nbr   = (const int*)  d_in[1];   // [131072, 9]
    const float* w0    = (const float*)d_in[2];   // [2304, 512]
    const float* wrest = (const float*)d_in[3];   // [7, 4608, 512]
    const float* gamma = (const float*)d_in[4];   // [8, 512]
    const float* beta  = (const float*)d_in[5];   // [8, 512]
    float* out = (float*)d_out;

    float *bufA, *bufB, *featr, *Wr;
    cudaGetSymbolAddress((void**)&bufA, g_bufA);
    cudaGetSymbolAddress((void**)&bufB, g_bufB);
    cudaGetSymbolAddress((void**)&featr, g_featr);
    cudaGetSymbolAddress((void**)&Wr, g_W);

    cudaFuncSetAttribute(spconv_mma<256, true>,
                         cudaFuncAttributeMaxDynamicSharedMemorySize, SMEM_BYTES);
    cudaFuncSetAttribute(spconv_mma<512, true>,
                         cudaFuncAttributeMaxDynamicSharedMemorySize, SMEM_BYTES);
    cudaFuncSetAttribute(spconv_mma<512, false>,
                         cudaFuncAttributeMaxDynamicSharedMemorySize, SMEM_BYTES);

    // Pre-round features + all weights to tf32 (RNA) so HW RZ truncation is exact.
    {
        const int f4 = NSITES * 256 / 4;
        round_copy<<<(f4 + 255) / 256, 256>>>(feat, featr, f4);
        const int w04 = (int)(W0_ELEMS / 4);
        round_copy<<<(w04 + 255) / 256, 256>>>(w0, Wr, w04);
        const int wl4 = (int)(7 * WL_ELEMS / 4);
        round_copy<<<(wl4 + 255) / 256, 256>>>(wrest, Wr + W0_ELEMS, wl4);
    }

    const dim3 grid(NSITES / 256, HID / 128);     // 512 x 4

    // layer 0: CIN=256
    spconv_mma<256, true><<<grid, 256, SMEM_BYTES>>>(featr, nbr, Wr, gamma, beta, bufA);

    const float* x = bufA;
    float*       y = bufB;
    for (int l = 1; l < 8; l++) {
        const float* wl = Wr + W0_ELEMS + (size_t)(l - 1) * WL_ELEMS;
        if (l == 7)
            spconv_mma<512, false><<<grid, 256, SMEM_BYTES>>>(
                x, nbr, wl, gamma + l * HID, beta + l * HID, out);
        else
            spconv_mma<512, true><<<grid, 256, SMEM_BYTES>>>(
                x, nbr, wl, gamma + l * HID, beta + l * HID, y);
        x = y;
        y = (y == bufB) ? bufA : bufB;
    }
}

// round 5
// speedup vs baseline: 3.4827x; 1.0118x over previous
#include <cuda_runtime.h>
#include <cstdint>
#include <cstddef>

#define NSITES 131072
#define HID    512
#define KTAPS  9
#define EPS    1e-5f

// ---------------------------------------------------------------------------
// Device-global scratch (allocation-free rule)
// ---------------------------------------------------------------------------
__device__ __align__(16) float g_bufA[(size_t)NSITES * HID];
__device__ __align__(16) float g_bufB[(size_t)NSITES * HID];
__device__ __align__(16) float g_featr[(size_t)NSITES * 256];
#define W0_ELEMS ((size_t)2304 * 512)
#define WL_ELEMS ((size_t)4608 * 512)
__device__ __align__(16) float g_W[W0_ELEMS + 7 * WL_ELEMS];

// ---------------------------------------------------------------------------
// Helpers (baseline PTX only — must pass ptxas at .target sm_103, no 'a' features)
// ---------------------------------------------------------------------------
__device__ __forceinline__ uint32_t smem_u32(const void* p) {
    uint32_t a;
    asm("{ .reg .u64 t; cvta.to.shared.u64 t, %1; cvt.u32.u64 %0, t; }" : "=r"(a) : "l"(p));
    return a;
}
__device__ __forceinline__ float tf32_rn(float v) {
    uint32_t o;
    asm("cvt.rna.tf32.f32 %0, %1;" : "=r"(o) : "f"(v));
    return __uint_as_float(o);
}
__device__ __forceinline__ void cp16(uint32_t dst, const void* src, int nbytes) {
    asm volatile("cp.async.cg.shared.global [%0], [%1], 16, %2;"
                 :: "r"(dst), "l"(src), "r"(nbytes));
}
#define CP_COMMIT() asm volatile("cp.async.commit_group;" ::: "memory")
#define CP_WAIT(n)  asm volatile("cp.async.wait_group %0;" :: "n"(n) : "memory")

// m16n8k8 tf32 MMA, fp32 accumulate (sm_80+ baseline PTX).
__device__ __forceinline__ void mma8(float& d0, float& d1, float& d2, float& d3,
                                     float a0, float a1, float a2, float a3,
                                     float b0, float b1) {
    asm volatile(
        "mma.sync.aligned.m16n8k8.row.col.f32.tf32.tf32.f32 "
        "{%0,%1,%2,%3}, {%4,%5,%6,%7}, {%8,%9}, {%0,%1,%2,%3};"
        : "+f"(d0), "+f"(d1), "+f"(d2), "+f"(d3)
        : "r"(__float_as_uint(a0)), "r"(__float_as_uint(a1)),
          "r"(__float_as_uint(a2)), "r"(__float_as_uint(a3)),
          "r"(__float_as_uint(b0)), "r"(__float_as_uint(b1)));
}

// ---------------------------------------------------------------------------
// SMEM layout (floats). k32 chunks:
//   A stage = 2 subtiles (k16 each) of [256 rows x 20 floats] (conflict-free)
//   B stage = [32 rows x 136 floats]                           (conflict-free)
// ---------------------------------------------------------------------------
#define A_STRIDE 20
#define SUB_SZ   (256 * A_STRIDE)       // 5120 floats per k16 subtile
#define A_SZ     (2 * SUB_SZ)           // 10240 floats / stage
#define B_STRIDE 136
#define B_SZ     (32 * B_STRIDE)        // 4352 floats / stage
#define STAGES   3
#define B_BASE   (STAGES * A_SZ)                    // 30720
#define SG_OFF   (B_BASE + STAGES * B_SZ)           // 43776
#define SB_OFF   (SG_OFF + 128)                     // 43904
#define IX_OFF   (SB_OFF + 128)                     // 44032
#define SMEM_FLOATS (IX_OFF + 256 * KTAPS)          // 46336
#define SMEM_BYTES  (SMEM_FLOATS * 4)               // 185344

// ===========================================================================
// Fused gather-GEMM (mma.sync tf32) + GroupNorm + ReLU.
// CTA: 256 sites x 128 out-channels, 8 warps (warp tile 64x64), k32 pipeline.
// ===========================================================================
template<int CIN, bool ROUND_OUT>
__global__ __launch_bounds__(256, 1)
void spconv_mma(const float* __restrict__ X, const int* __restrict__ nbr,
                const float* __restrict__ W,       // [KTAPS*CIN, 512] row-major, tf32-rounded
                const float* __restrict__ gamma, const float* __restrict__ beta,
                float* __restrict__ Y)
{
    constexpr int KTOT = KTAPS * CIN;
    constexpr int NCH  = KTOT / 32;     // k-chunks of 32
    constexpr int CPT  = CIN / 32;      // chunks per tap (8 or 16; never crosses taps)

    extern __shared__ float sm[];
    const uint32_t smbase = smem_u32(sm);
    int* sidx = (int*)(sm + IX_OFF);

    const int tid = threadIdx.x;
    const int m0  = blockIdx.x * 256;
    const int n0  = blockIdx.y * 128;

    for (int i = tid; i < 128; i += 256) {
        sm[SG_OFF + i] = gamma[n0 + i];
        sm[SB_OFF + i] = beta[n0 + i];
    }
    for (int i = tid; i < 256 * KTAPS; i += 256)
        sidx[i] = nbr[(size_t)m0 * KTAPS + i];
    __syncthreads();

    const int warp = tid >> 5, lane = tid & 31;
    const int wm  = (warp >> 1) * 64;   // warp M offset: 0,64,128,192
    const int wn  = (warp & 1) * 64;    // warp N offset: 0,64
    const int gid = lane >> 2;          // 0..7
    const int q   = lane & 3;           // 0..3

    float d[4][8][4];
    #pragma unroll
    for (int i = 0; i < 4; i++)
        #pragma unroll
        for (int j = 0; j < 8; j++)
            #pragma unroll
            for (int r = 0; r < 4; r++) d[i][j][r] = 0.f;

    // ---- async load of one k32 chunk into stage s ----
    auto load_chunk = [&](int ch, int s) {
        const int tap = ch / CPT;
        const int c0  = (ch - tap * CPT) * 32;
        const uint32_t abase = smbase + (uint32_t)s * (A_SZ * 4);
        #pragma unroll
        for (int t = 0; t < 8; t++) {               // 2048 A granules (256 rows x 8)
            const int g   = tid + (t << 8);
            const int row = g >> 3, kq = g & 7;
            const int sub = kq >> 2, kk = kq & 3;
            const int nid = sidx[row * KTAPS + tap];
            const float* src = X + (size_t)(nid < 0 ? 0 : nid) * CIN + c0 + kq * 4;
            cp16(abase + (uint32_t)(sub * (SUB_SZ * 4) + row * 80 + kk * 16),
                 src, nid < 0 ? 0 : 16);
        }
        const uint32_t bbase = smbase + (uint32_t)(B_BASE * 4) + (uint32_t)s * (B_SZ * 4);
        const float* wb = W + (size_t)ch * 32 * HID + n0;
        #pragma unroll
        for (int t = 0; t < 4; t++) {               // 1024 B granules (32 rows x 32)
            const int g  = tid + (t << 8);
            const int kr = g >> 5, ns = g & 31;
            cp16(bbase + (uint32_t)(kr * 544 + ns * 16), wb + (size_t)kr * HID + ns * 4, 16);
        }
    };

    // ---- compute one k32 chunk from stage s (4 k8 steps, same order as before) ----
    auto compute = [&](int s) {
        const float* Astage = sm + s * A_SZ;
        const float* Bf     = sm + B_BASE + s * B_SZ;
        #pragma unroll
        for (int k8 = 0; k8 < 4; k8++) {
            const float* Af = Astage + (k8 >> 1) * SUB_SZ;
            const int c = (k8 & 1) * 8 + q;
            const int k = k8 * 8 + q;
            float a[4][4];
            #pragma unroll
            for (int mt = 0; mt < 4; mt++) {
                const int r = wm + mt * 16 + gid;
                a[mt][0] = Af[r * A_STRIDE + c];
                a[mt][1] = Af[(r + 8) * A_STRIDE + c];
                a[mt][2] = Af[r * A_STRIDE + c + 4];
                a[mt][3] = Af[(r + 8) * A_STRIDE + c + 4];
            }
            #pragma unroll
            for (int nt = 0; nt < 8; nt++) {
                const int n = wn + nt * 8 + gid;
                const float b0 = Bf[k * B_STRIDE + n];
                const float b1 = Bf[(k + 4) * B_STRIDE + n];
                #pragma unroll
                for (int mt = 0; mt < 4; mt++)
                    mma8(d[mt][nt][0], d[mt][nt][1], d[mt][nt][2], d[mt][nt][3],
                         a[mt][0], a[mt][1], a[mt][2], a[mt][3], b0, b1);
            }
        }
    };

    // ---- 3-stage pipelined mainloop (one barrier per k32 chunk) ----
    load_chunk(0, 0); CP_COMMIT();
    load_chunk(1, 1); CP_COMMIT();
    #pragma unroll 1
    for (int ch = 0; ch < NCH; ch++) {
        CP_WAIT(1);                     // stage ch resident (this thread)
        __syncthreads();                // visible to all; stage (ch-1)%3 free
        if (ch + 2 < NCH) load_chunk(ch + 2, (ch + 2) % STAGES);
        CP_COMMIT();
        compute(ch % STAGES);
    }

    // ---- fused GroupNorm(16-ch groups) + ReLU epilogue ----
    #pragma unroll
    for (int mt = 0; mt < 4; mt++) {
        #pragma unroll
        for (int h = 0; h < 2; h++) {
            const int row = m0 + wm + mt * 16 + gid + h * 8;
            float* yr = Y + (size_t)row * HID + n0 + wn;
            #pragma unroll
            for (int g = 0; g < 4; g++) {
                const float v0 = d[mt][2 * g    ][2 * h];
                const float v1 = d[mt][2 * g    ][2 * h + 1];
                const float v2 = d[mt][2 * g + 1][2 * h];
                const float v3 = d[mt][2 * g + 1][2 * h + 1];
                float s  = v0 + v1 + v2 + v3;
                float ss = v0 * v0 + v1 * v1 + v2 * v2 + v3 * v3;
                s  += __shfl_xor_sync(0xffffffffu, s, 1);
                ss += __shfl_xor_sync(0xffffffffu, ss, 1);
                s  += __shfl_xor_sync(0xffffffffu, s, 2);
                ss += __shfl_xor_sync(0xffffffffu, ss, 2);
                const float mu  = s * (1.f / 16.f);
                const float var = ss * (1.f / 16.f) - mu * mu;
                const float rs  = rsqrtf(var + EPS);
                const int cb = wn + 16 * g + 2 * q;       // local col in [0,128)
                float o0 = fmaxf(fmaf((v0 - mu) * rs, sm[SG_OFF + cb],     sm[SB_OFF + cb]),     0.f);
                float o1 = fmaxf(fmaf((v1 - mu) * rs, sm[SG_OFF + cb + 1], sm[SB_OFF + cb + 1]), 0.f);
                float o2 = fmaxf(fmaf((v2 - mu) * rs, sm[SG_OFF + cb + 8], sm[SB_OFF + cb + 8]), 0.f);
                float o3 = fmaxf(fmaf((v3 - mu) * rs, sm[SG_OFF + cb + 9], sm[SB_OFF + cb + 9]), 0.f);
                if (ROUND_OUT) {
                    o0 = tf32_rn(o0); o1 = tf32_rn(o1);
                    o2 = tf32_rn(o2); o3 = tf32_rn(o3);
                }
                *(float2*)(yr + 16 * g + 2 * q)     = make_float2(o0, o1);
                *(float2*)(yr + 16 * g + 8 + 2 * q) = make_float2(o2, o3);
            }
        }
    }
}

// ---------------------------------------------------------------------------
// tf32-RNA rounding copy (float4 per thread)
// ---------------------------------------------------------------------------
__global__ void round_copy(const float* __restrict__ src, float* __restrict__ dst, int n4)
{
    const int t = blockIdx.x * blockDim.x + threadIdx.x;
    if (t >= n4) return;
    float4 v = ((const float4*)src)[t];
    v.x = tf32_rn(v.x); v.y = tf32_rn(v.y);
    v.z = tf32_rn(v.z); v.w = tf32_rn(v.w);
    ((float4*)dst)[t] = v;
}

// ===========================================================================
// kernel_launch: prep (round) + 8 fused layers, ping-pong buffers.
// ===========================================================================
extern "C" void kernel_launch(void* const* d_in, const int* in_sizes, int n_in,
                              void* d_out, int out_size)
{
    const float* feat  = (const float*)d_in[0];   // [131072, 256]
    const int*   nbr   = (const int*)  d_in[1];   // [131072, 9]
    const float* w0    = (const float*)d_in[2];   // [2304, 512]
    const float* wrest = (const float*)d_in[3];   // [7, 4608, 512]
    const float* gamma = (const float*)d_in[4];   // [8, 512]
    const float* beta  = (const float*)d_in[5];   // [8, 512]
    float* out = (float*)d_out;

    float *bufA, *bufB, *featr, *Wr;
    cudaGetSymbolAddress((void**)&bufA, g_bufA);
    cudaGetSymbolAddress((void**)&bufB, g_bufB);
    cudaGetSymbolAddress((void**)&featr, g_featr);
    cudaGetSymbolAddress((void**)&Wr, g_W);

    cudaFuncSetAttribute(spconv_mma<256, true>,
                         cudaFuncAttributeMaxDynamicSharedMemorySize, SMEM_BYTES);
    cudaFuncSetAttribute(spconv_mma<512, true>,
                         cudaFuncAttributeMaxDynamicSharedMemorySize, SMEM_BYTES);
    cudaFuncSetAttribute(spconv_mma<512, false>,
                         cudaFuncAttributeMaxDynamicSharedMemorySize, SMEM_BYTES);

    // Pre-round features + all weights to tf32 (RNA) so HW truncation is exact.
    {
        const int f4 = NSITES * 256 / 4;
        round_copy<<<(f4 + 255) / 256, 256>>>(feat, featr, f4);
        const int w04 = (int)(W0_ELEMS / 4);
        round_copy<<<(w04 + 255) / 256, 256>>>(w0, Wr, w04);
        const int wl4 = (int)(7 * WL_ELEMS / 4);
        round_copy<<<(wl4 + 255) / 256, 256>>>(wrest, Wr + W0_ELEMS, wl4);
    }

    const dim3 grid(NSITES / 256, HID / 128);     // 512 x 4

    // layer 0: CIN=256
    spconv_mma<256, true><<<grid, 256, SMEM_BYTES>>>(featr, nbr, Wr, gamma, beta, bufA);

    const float* x = bufA;
    float*       y = bufB;
    for (int l = 1; l < 8; l++) {
        const float* wl = Wr + W0_ELEMS + (size_t)(l - 1) * WL_ELEMS;
        if (l == 7)
            spconv_mma<512, false><<<grid, 256, SMEM_BYTES>>>(
                x, nbr, wl, gamma + l * HID, beta + l * HID, out);
        else
            spconv_mma<512, true><<<grid, 256, SMEM_BYTES>>>(
                x, nbr, wl, gamma + l * HID, beta + l * HID, y);
        x = y;
        y = (y == bufB) ? bufA : bufB;
    }
}